// round 9
// baseline (speedup 1.0000x reference)
#include <cuda_runtime.h>
#include <math.h>

#define NPART 512
#define NB    16
#define HIDN  100
#define WPB   2            // warps per block (main kernel)
#define NI    4            // particles i per warp
#define TPB   64

typedef unsigned long long u64;

// ---- device-global scratch (no allocations allowed) ----
// pair-interleaved packed per-j constants; gP*[b*256+idx] covers j=2*idx,2*idx+1
// gP0 = { -y pair, -x pair }    gP1 = { ml2e pair, mc pair }
// gP2 = { md pair, tau/2pi pair } gP3 = { 1/sig^2 pair, -c/2 pair }
__device__ ulonglong2 gP0[NB * NPART / 2];
__device__ ulonglong2 gP1[NB * NPART / 2];
__device__ ulonglong2 gP2[NB * NPART / 2];
__device__ ulonglong2 gP3[NB * NPART / 2];
__device__ float      gW2T[6 * HIDN];      // gW2T[m*HIDN+k] = W2[k*6+m]

__device__ __forceinline__ float ex2f(float x) {
    float y; asm("ex2.approx.ftz.f32 %0, %1;" : "=f"(y) : "f"(x)); return y;
}
__device__ __forceinline__ float lg2f(float x) {
    float y; asm("lg2.approx.ftz.f32 %0, %1;" : "=f"(y) : "f"(x)); return y;
}
__device__ __forceinline__ float rsq_a(float x) {
    float y; asm("rsqrt.approx.ftz.f32 %0, %1;" : "=f"(y) : "f"(x)); return y;
}
__device__ __forceinline__ float rcp_a(float x) {
    float y; asm("rcp.approx.ftz.f32 %0, %1;" : "=f"(y) : "f"(x)); return y;
}

// fast softplus: max(x,0) + ln(1+exp(-|x|)) via ex2/lg2
__device__ __forceinline__ float softplus_fast(float x) {
    const float L2E = 1.4426950408889634f;
    const float LN2 = 0.6931471805599453f;
    float e = ex2f(-fabsf(x) * L2E);
    float l = lg2f(1.0f + e) * LN2;
    return fmaxf(x, 0.0f) + l;
}

// ---- packed f32x2 helpers (sm_100+) ----
__device__ __forceinline__ u64 pk2(float lo, float hi) {
    u64 d; asm("mov.b64 %0, {%1, %2};" : "=l"(d) : "f"(lo), "f"(hi)); return d;
}
__device__ __forceinline__ void upk2(u64 v, float& lo, float& hi) {
    asm("mov.b64 {%0, %1}, %2;" : "=f"(lo), "=f"(hi) : "l"(v));
}
__device__ __forceinline__ u64 fma2(u64 a, u64 b, u64 c) {
    u64 d; asm("fma.rn.f32x2 %0, %1, %2, %3;" : "=l"(d) : "l"(a), "l"(b), "l"(c)); return d;
}
__device__ __forceinline__ u64 mul2(u64 a, u64 b) {
    u64 d; asm("mul.rn.f32x2 %0, %1, %2;" : "=l"(d) : "l"(a), "l"(b)); return d;
}
__device__ __forceinline__ u64 add2(u64 a, u64 b) {
    u64 d; asm("add.rn.f32x2 %0, %1, %2;" : "=l"(d) : "l"(a), "l"(b)); return d;
}
__device__ __forceinline__ u64 ex2p(u64 a) {
    float lo, hi; upk2(a, lo, hi);
    return pk2(ex2f(lo), ex2f(hi));
}
__device__ __forceinline__ u64 rsqp(u64 a) {
    float lo, hi; upk2(a, lo, hi);
    return pk2(rsq_a(lo), rsq_a(hi));
}

struct Acc { u64 vyp, vx, F, G, Gxx, Gyy; };

// per-pair vortex interaction (packed 2 j's). Accumulates vyp = +Sum F*dx.
// q1 = {ml2e, mc}, q2 = {md, t2p}, q3 = {is2, -c/2}, nddv = -d
__device__ __forceinline__ void pair_body(
    u64 yi2, u64 xi2, const ulonglong2& q0, const ulonglong2& q1,
    const ulonglong2& q2, const ulonglong2& q3, u64 nddv, Acc& a,
    u64 ones, u64 nones, u64 eps2)
{
    u64 dy  = add2(yi2, q0.x);                 // yi - yj
    u64 dx  = add2(xi2, q0.y);                 // xi - xj
    u64 sq  = fma2(dy, dy, mul2(dx, dx));
    u64 s   = add2(sq, eps2);
    u64 rs  = rsqp(s);                         // 1/sqrt(s)
    u64 r   = mul2(s, rs);                     // sqrt(s)
    u64 ivs = mul2(rs, rs);                    // 1/s
    u64 e1  = ex2p(mul2(sq, q1.x));            // exp(-sq/sig^2)
    u64 e2  = ex2p(fma2(q1.y, r, mul2(q2.x, sq))); // exp(-c r - d sq)
    u64 g   = fma2(e1, nones, ones);           // 1 - e1 (== 0 for j==i)
    u64 A   = mul2(q2.y, ivs);                 // tau/(2 pi s)
    u64 Ae2 = mul2(A, e2);
    u64 F   = mul2(Ae2, g);                    // falloff
    u64 is2e1 = mul2(q3.x, e1);
    u64 mivs  = fma2(ivs, nones, nddv);        // -d - 1/s
    u64 t2n   = fma2(q3.y, rs, mivs);          // -(c/(2r) + d + 1/s)
    u64 inner = fma2(g, t2n, is2e1);           // is2*e1 - g*t2
    u64 Fp  = mul2(Ae2, inner);                // dF/d(sq)
    u64 G2  = add2(Fp, Fp);
    a.vyp = fma2(F, dx, a.vyp);
    a.vx  = fma2(F, dy, a.vx);
    a.F   = add2(a.F, F);
    u64 gdy = mul2(G2, dy);
    u64 gdx = mul2(G2, dx);
    a.G   = fma2(gdy, dx, a.G);
    a.Gxx = fma2(gdx, dx, a.Gxx);
    a.Gyy = fma2(gdy, dy, a.Gyy);
}

// ---- precompute kernel: packs per-particle constants + W2 transpose ----
__global__ __launch_bounds__(128)
void prep_kernel(const float* __restrict__ inp, const float* __restrict__ W2)
{
    const float L2E    = 1.4426950408889634f;
    const float INV2PI = 0.15915494309189535f;
    int p = blockIdx.x * blockDim.x + threadIdx.x;   // 0..8191
    if (p < NB * NPART) {
        float y   = inp[p * 6 + 0];
        float x   = inp[p * 6 + 1];
        float tau = inp[p * 6 + 2];
        float sig = inp[p * 6 + 3];
        float c   = inp[p * 6 + 4];
        float d   = inp[p * 6 + 5];
        float is2 = rcp_a(sig * sig);
        int idx = p >> 1;
        int o   = p & 1;
        float* f0 = (float*)gP0;
        float* f1 = (float*)gP1;
        float* f2 = (float*)gP2;
        float* f3 = (float*)gP3;
        f0[idx * 4 + 0 + o] = -y;
        f0[idx * 4 + 2 + o] = -x;
        f1[idx * 4 + 0 + o] = -is2 * L2E;   // ml2e
        f1[idx * 4 + 2 + o] = -c * L2E;     // mc
        f2[idx * 4 + 0 + o] = -d * L2E;     // md
        f2[idx * 4 + 2 + o] = tau * INV2PI; // t2p
        f3[idx * 4 + 0 + o] = is2;
        f3[idx * 4 + 2 + o] = -0.5f * c;    // nhc
    }
    if (p < HIDN * 6) {
        int k = p / 6, m = p % 6;
        gW2T[m * HIDN + k] = W2[p];
    }
}

// ---- main kernel: 64 threads, 4 particles/warp, j-data staged in smem ----
__global__ __launch_bounds__(TPB, 7)
void vortex_main_kernel(const float* __restrict__ inp,
                        const float* __restrict__ W1,
                        const float* __restrict__ b1,
                        const float* __restrict__ b2,
                        float* __restrict__ out)
{
    __shared__ ulonglong2 S0[NPART / 2], S1[NPART / 2], S2[NPART / 2], S3[NPART / 2];

    const int tid   = threadIdx.x;
    const int ipb   = WPB * NI;                // 8 i's per block
    const int bpb   = NPART / ipb;             // 64 blocks per batch
    const int b     = blockIdx.x / bpb;
    const int ig    = blockIdx.x % bpb;
    const int warp  = tid >> 5;
    const int lane  = tid & 31;
    const int ibase = ig * ipb + warp * NI;    // this warp's first particle

    const float LN2 = 0.6931471805599453f;

    // per-i scalars (independent of staging; issue first)
    const float* pp[NI];
    float yi[NI], xi[NI];
    u64 yp[NI], xp[NI];
    #pragma unroll
    for (int q = 0; q < NI; ++q) {
        pp[q] = inp + ((size_t)b * NPART + ibase + q) * 6;
        yi[q] = __ldg(pp[q] + 0);
        xi[q] = __ldg(pp[q] + 1);
        yp[q] = pk2(yi[q], yi[q]);
        xp[q] = pk2(xi[q], xi[q]);
    }

    // ---- stage packed j-data into shared memory (coalesced 128B streams) ----
    {
        const ulonglong2* __restrict__ Pg0 = gP0 + (size_t)b * (NPART / 2);
        const ulonglong2* __restrict__ Pg1 = gP1 + (size_t)b * (NPART / 2);
        const ulonglong2* __restrict__ Pg2 = gP2 + (size_t)b * (NPART / 2);
        const ulonglong2* __restrict__ Pg3 = gP3 + (size_t)b * (NPART / 2);
        #pragma unroll
        for (int t = tid; t < NPART / 2; t += TPB) {
            S0[t] = Pg0[t];
            S1[t] = Pg1[t];
            S2[t] = Pg2[t];
            S3[t] = Pg3[t];
        }
    }
    __syncthreads();

    const u64 ones  = pk2(1.0f, 1.0f);
    const u64 nones = pk2(-1.0f, -1.0f);
    const u64 eps2  = pk2(1e-6f, 1e-6f);
    const u64 pln2  = pk2(LN2, LN2);

    Acc acc[NI];
    #pragma unroll
    for (int q = 0; q < NI; ++q) acc[q] = (Acc){0,0,0,0,0,0};

    #pragma unroll 2
    for (int jj = 0; jj < NPART / 64; ++jj) {
        int idx = jj * 32 + lane;
        ulonglong2 q0 = S0[idx];
        ulonglong2 q1 = S1[idx];
        ulonglong2 q2 = S2[idx];
        ulonglong2 q3 = S3[idx];
        u64 nddv = mul2(q2.x, pln2);           // -d = md * ln2
        #pragma unroll
        for (int q = 0; q < NI; ++q)
            pair_body(yp[q], xp[q], q0, q1, q2, q3, nddv, acc[q],
                      ones, nones, eps2);
    }

    // ---- horizontal add of packed halves, then warp butterfly reduce ----
    float red[6 * NI];
    #pragma unroll
    for (int q = 0; q < NI; ++q) {
        float l, h;
        upk2(acc[q].vyp, l, h); red[q * 6 + 0] = l + h;
        upk2(acc[q].vx,  l, h); red[q * 6 + 1] = l + h;
        upk2(acc[q].F,   l, h); red[q * 6 + 2] = l + h;
        upk2(acc[q].G,   l, h); red[q * 6 + 3] = l + h;
        upk2(acc[q].Gxx, l, h); red[q * 6 + 4] = l + h;
        upk2(acc[q].Gyy, l, h); red[q * 6 + 5] = l + h;
    }
    #pragma unroll
    for (int o = 16; o; o >>= 1) {
        #pragma unroll
        for (int m = 0; m < 6 * NI; ++m)
            red[m] += __shfl_xor_sync(0xffffffffu, red[m], o);
    }

    // features: tau, sig, c, d, vy, vx, dvy/dy, dvy/dx, dvx/dy, dvx/dx
    float feat[NI][10];
    float tau_[NI], sig_[NI];
    #pragma unroll
    for (int q = 0; q < NI; ++q) {
        tau_[q] = __ldg(pp[q] + 2);
        sig_[q] = __ldg(pp[q] + 3);
        feat[q][0] = tau_[q];
        feat[q][1] = sig_[q];
        feat[q][2] = __ldg(pp[q] + 4);
        feat[q][3] = __ldg(pp[q] + 5);
        feat[q][4] = -red[q * 6 + 0];                    // vy
        feat[q][5] = red[q * 6 + 1];                     // vx
        feat[q][6] = -red[q * 6 + 3];                    // dvy/dy
        feat[q][7] = -(red[q * 6 + 4] + red[q * 6 + 2]); // dvy/dx
        feat[q][8] = red[q * 6 + 5] + red[q * 6 + 2];    // dvx/dy
        feat[q][9] = red[q * 6 + 3];                     // dvx/dx
    }

    // ---- MLP 10 -> 100 (LeakyReLU 0.1) -> 6, weights shared across 4 i's ----
    float po[NI][6];
    #pragma unroll
    for (int q = 0; q < NI; ++q)
        #pragma unroll
        for (int m = 0; m < 6; ++m) po[q][m] = 0.0f;

    #pragma unroll
    for (int rblk = 0; rblk < 4; ++rblk) {
        int k = rblk * 32 + lane;
        if (k < HIDN) {
            float h[NI];
            float bb = __ldg(&b1[k]);
            #pragma unroll
            for (int q = 0; q < NI; ++q) h[q] = bb;
            #pragma unroll
            for (int f = 0; f < 10; ++f) {
                float w = __ldg(&W1[f * HIDN + k]);
                #pragma unroll
                for (int q = 0; q < NI; ++q) h[q] = fmaf(feat[q][f], w, h[q]);
            }
            #pragma unroll
            for (int q = 0; q < NI; ++q)
                h[q] = (h[q] >= 0.0f) ? h[q] : 0.1f * h[q];
            #pragma unroll
            for (int m = 0; m < 6; ++m) {
                float w = __ldg(&gW2T[m * HIDN + k]);
                #pragma unroll
                for (int q = 0; q < NI; ++q) po[q][m] = fmaf(h[q], w, po[q][m]);
            }
        }
    }
    #pragma unroll
    for (int o = 16; o; o >>= 1) {
        #pragma unroll
        for (int q = 0; q < NI; ++q)
            #pragma unroll
            for (int m = 0; m < 6; ++m)
                po[q][m] += __shfl_xor_sync(0xffffffffu, po[q][m], o);
    }

    // ---- epilogue (lane 0 writes all 4 particles, float2 stores) ----
    if (lane == 0) {
        float bb0 = __ldg(&b2[0]), bb1 = __ldg(&b2[1]), bb2 = __ldg(&b2[2]);
        float bb3 = __ldg(&b2[3]), bb4 = __ldg(&b2[4]), bb5 = __ldg(&b2[5]);
        #pragma unroll
        for (int q = 0; q < NI; ++q) {
            float2* op = (float2*)(out + ((size_t)b * NPART + ibase + q) * 6);
            op[0] = make_float2(yi[q]   + 0.1f * (po[q][0] + bb0),
                                xi[q]   + 0.1f * (po[q][1] + bb1));
            op[1] = make_float2(tau_[q] + 0.1f * (po[q][2] + bb2),
                                sig_[q] + 0.1f * (po[q][3] + bb3));
            op[2] = make_float2(0.1f * softplus_fast(po[q][4] + bb4),
                                0.1f * softplus_fast(po[q][5] + bb5));
        }
    }
}

extern "C" void kernel_launch(void* const* d_in, const int* in_sizes, int n_in,
                              void* d_out, int out_size)
{
    const float* inp = (const float*)d_in[0];  // (16,512,6)
    const float* W1  = (const float*)d_in[1];  // (10,100)
    const float* b1  = (const float*)d_in[2];  // (100,)
    const float* W2  = (const float*)d_in[3];  // (100,6)
    const float* b2  = (const float*)d_in[4];  // (6,)
    float* out = (float*)d_out;                // (16,512,6)

    // 1) pack per-particle constants + W2 transpose into device-global scratch
    prep_kernel<<<(NB * NPART + 127) / 128, 128>>>(inp, W2);
    // 2) main fused kernel: 1024 blocks of 64 threads, smem-staged j-data
    dim3 grid(NB * (NPART / (WPB * NI)));      // 1024
    vortex_main_kernel<<<grid, TPB>>>(inp, W1, b1, b2, out);
}

// round 10
// speedup vs baseline: 1.1451x; 1.1451x over previous
#include <cuda_runtime.h>
#include <math.h>

#define NPART 512
#define NB    16
#define HIDN  100
#define WPB   2            // warps per block
#define NI    4            // particles i per warp
#define TPB   64

typedef unsigned long long u64;

__device__ __forceinline__ float ex2f(float x) {
    float y; asm("ex2.approx.ftz.f32 %0, %1;" : "=f"(y) : "f"(x)); return y;
}
__device__ __forceinline__ float lg2f(float x) {
    float y; asm("lg2.approx.ftz.f32 %0, %1;" : "=f"(y) : "f"(x)); return y;
}
__device__ __forceinline__ float rsq_a(float x) {
    float y; asm("rsqrt.approx.ftz.f32 %0, %1;" : "=f"(y) : "f"(x)); return y;
}
__device__ __forceinline__ float rcp_a(float x) {
    float y; asm("rcp.approx.ftz.f32 %0, %1;" : "=f"(y) : "f"(x)); return y;
}

// fast softplus: max(x,0) + ln(1+exp(-|x|)) via ex2/lg2
__device__ __forceinline__ float softplus_fast(float x) {
    const float L2E = 1.4426950408889634f;
    const float LN2 = 0.6931471805599453f;
    float e = ex2f(-fabsf(x) * L2E);
    float l = lg2f(1.0f + e) * LN2;
    return fmaxf(x, 0.0f) + l;
}

// ---- packed f32x2 helpers (sm_100+) ----
__device__ __forceinline__ u64 pk2(float lo, float hi) {
    u64 d; asm("mov.b64 %0, {%1, %2};" : "=l"(d) : "f"(lo), "f"(hi)); return d;
}
__device__ __forceinline__ void upk2(u64 v, float& lo, float& hi) {
    asm("mov.b64 {%0, %1}, %2;" : "=f"(lo), "=f"(hi) : "l"(v));
}
__device__ __forceinline__ u64 fma2(u64 a, u64 b, u64 c) {
    u64 d; asm("fma.rn.f32x2 %0, %1, %2, %3;" : "=l"(d) : "l"(a), "l"(b), "l"(c)); return d;
}
__device__ __forceinline__ u64 mul2(u64 a, u64 b) {
    u64 d; asm("mul.rn.f32x2 %0, %1, %2;" : "=l"(d) : "l"(a), "l"(b)); return d;
}
__device__ __forceinline__ u64 add2(u64 a, u64 b) {
    u64 d; asm("add.rn.f32x2 %0, %1, %2;" : "=l"(d) : "l"(a), "l"(b)); return d;
}
__device__ __forceinline__ u64 ex2p(u64 a) {
    float lo, hi; upk2(a, lo, hi);
    return pk2(ex2f(lo), ex2f(hi));
}
__device__ __forceinline__ u64 rsqp(u64 a) {
    float lo, hi; upk2(a, lo, hi);
    return pk2(rsq_a(lo), rsq_a(hi));
}
__device__ __forceinline__ u64 rcpp(u64 a) {
    float lo, hi; upk2(a, lo, hi);
    return pk2(rcp_a(lo), rcp_a(hi));
}

struct Acc { u64 vyp, vx, F, G, Gxx, Gyy; };

// per-pair vortex interaction (packed 2 j's). Accumulates vyp = +Sum F*dx.
// yj/xj are raw (positive); ml2e={-is2*log2e}, mc={-c*log2e}, md={-d*log2e},
// t2p={tau/2pi}, is2={1/sig^2}, nhc={-c/2}, ndd={-d}
__device__ __forceinline__ void pair_body(
    u64 yi2, u64 xi2, u64 yj, u64 xj, u64 ml2e, u64 mc, u64 md,
    u64 t2p, u64 is2, u64 nhc, u64 ndd, Acc& a,
    u64 ones, u64 nones, u64 eps2)
{
    u64 dy  = fma2(yj, nones, yi2);            // yi - yj
    u64 dx  = fma2(xj, nones, xi2);            // xi - xj
    u64 sq  = fma2(dy, dy, mul2(dx, dx));
    u64 s   = add2(sq, eps2);
    u64 rs  = rsqp(s);                         // 1/sqrt(s)
    u64 r   = mul2(s, rs);                     // sqrt(s)
    u64 ivs = mul2(rs, rs);                    // 1/s
    u64 e1  = ex2p(mul2(sq, ml2e));            // exp(-sq/sig^2)
    u64 e2  = ex2p(fma2(mc, r, mul2(md, sq))); // exp(-c r - d sq)
    u64 g   = fma2(e1, nones, ones);           // 1 - e1 (== 0 for j==i)
    u64 A   = mul2(t2p, ivs);                  // tau/(2 pi s)
    u64 Ae2 = mul2(A, e2);
    u64 F   = mul2(Ae2, g);                    // falloff
    u64 is2e1 = mul2(is2, e1);
    u64 mivs  = fma2(ivs, nones, ndd);         // -d - 1/s
    u64 t2n   = fma2(nhc, rs, mivs);           // -(c/(2r) + d + 1/s)
    u64 inner = fma2(g, t2n, is2e1);           // is2*e1 - g*t2
    u64 Fp  = mul2(Ae2, inner);                // dF/d(sq)
    u64 G2  = add2(Fp, Fp);
    a.vyp = fma2(F, dx, a.vyp);
    a.vx  = fma2(F, dy, a.vx);
    a.F   = add2(a.F, F);
    u64 gdy = mul2(G2, dy);
    u64 gdx = mul2(G2, dx);
    a.G   = fma2(gdy, dx, a.G);
    a.Gxx = fma2(gdx, dx, a.Gxx);
    a.Gyy = fma2(gdy, dy, a.Gyy);
}

// ---- single fused kernel: raw-input mainloop, no prep, no smem ----
__global__ __launch_bounds__(TPB, 7)
void vortex_kernel(const float* __restrict__ inp,
                   const float* __restrict__ W1,
                   const float* __restrict__ b1,
                   const float* __restrict__ W2,
                   const float* __restrict__ b2,
                   float* __restrict__ out)
{
    const int tid   = threadIdx.x;
    const int ipb   = WPB * NI;                // 8 i's per block
    const int bpb   = NPART / ipb;             // 64 blocks per batch
    const int b     = blockIdx.x / bpb;
    const int ig    = blockIdx.x % bpb;
    const int warp  = tid >> 5;
    const int lane  = tid & 31;
    const int ibase = ig * ipb + warp * NI;    // this warp's first particle

    const float L2E    = 1.4426950408889634f;
    const float INV2PI = 0.15915494309189535f;

    // per-i scalars
    const float* pp[NI];
    float yi[NI], xi[NI];
    u64 yp[NI], xp[NI];
    #pragma unroll
    for (int q = 0; q < NI; ++q) {
        pp[q] = inp + ((size_t)b * NPART + ibase + q) * 6;
        yi[q] = __ldg(pp[q] + 0);
        xi[q] = __ldg(pp[q] + 1);
        yp[q] = pk2(yi[q], yi[q]);
        xp[q] = pk2(xi[q], xi[q]);
    }

    const u64 ones   = pk2(1.0f, 1.0f);
    const u64 nones  = pk2(-1.0f, -1.0f);
    const u64 eps2   = pk2(1e-6f, 1e-6f);
    const u64 nl2e   = pk2(-L2E, -L2E);
    const u64 pi2p   = pk2(INV2PI, INV2PI);
    const u64 nhalf  = pk2(-0.5f, -0.5f);

    // batch base as float4 stream: 12 floats per packed j-pair = 3 float4
    const float4* __restrict__ ip4 = (const float4*)(inp + (size_t)b * NPART * 6);

    Acc acc[NI];
    #pragma unroll
    for (int q = 0; q < NI; ++q) acc[q] = (Acc){0,0,0,0,0,0};

    #pragma unroll 2
    for (int jj = 0; jj < NPART / 64; ++jj) {
        int idx = jj * 32 + lane;              // packed j-pair index (0..255)
        float4 A4 = __ldg(&ip4[idx * 3 + 0]);  // y0 x0 tau0 sig0
        float4 B4 = __ldg(&ip4[idx * 3 + 1]);  // c0 d0 y1 x1
        float4 C4 = __ldg(&ip4[idx * 3 + 2]);  // tau1 sig1 c1 d1

        u64 yj   = pk2(A4.x, B4.z);
        u64 xj   = pk2(A4.y, B4.w);
        u64 tauv = pk2(A4.z, C4.x);
        u64 sigv = pk2(A4.w, C4.y);
        u64 cv   = pk2(B4.x, C4.z);
        u64 dv   = pk2(B4.y, C4.w);

        u64 is2  = rcpp(mul2(sigv, sigv));     // 1/sig^2
        u64 ml2e = mul2(is2, nl2e);            // -is2*log2e
        u64 mc   = mul2(cv, nl2e);             // -c*log2e
        u64 md   = mul2(dv, nl2e);             // -d*log2e
        u64 t2p  = mul2(tauv, pi2p);           // tau/2pi
        u64 nhc  = mul2(cv, nhalf);            // -c/2
        u64 ndd  = mul2(dv, nones);            // -d

        #pragma unroll
        for (int q = 0; q < NI; ++q)
            pair_body(yp[q], xp[q], yj, xj, ml2e, mc, md, t2p, is2, nhc, ndd,
                      acc[q], ones, nones, eps2);
    }

    // ---- horizontal add of packed halves, then warp butterfly reduce ----
    float red[6 * NI];
    #pragma unroll
    for (int q = 0; q < NI; ++q) {
        float l, h;
        upk2(acc[q].vyp, l, h); red[q * 6 + 0] = l + h;
        upk2(acc[q].vx,  l, h); red[q * 6 + 1] = l + h;
        upk2(acc[q].F,   l, h); red[q * 6 + 2] = l + h;
        upk2(acc[q].G,   l, h); red[q * 6 + 3] = l + h;
        upk2(acc[q].Gxx, l, h); red[q * 6 + 4] = l + h;
        upk2(acc[q].Gyy, l, h); red[q * 6 + 5] = l + h;
    }
    #pragma unroll
    for (int o = 16; o; o >>= 1) {
        #pragma unroll
        for (int m = 0; m < 6 * NI; ++m)
            red[m] += __shfl_xor_sync(0xffffffffu, red[m], o);
    }

    // features: tau, sig, c, d, vy, vx, dvy/dy, dvy/dx, dvx/dy, dvx/dx
    float feat[NI][10];
    float tau_[NI], sig_[NI];
    #pragma unroll
    for (int q = 0; q < NI; ++q) {
        tau_[q] = __ldg(pp[q] + 2);
        sig_[q] = __ldg(pp[q] + 3);
        feat[q][0] = tau_[q];
        feat[q][1] = sig_[q];
        feat[q][2] = __ldg(pp[q] + 4);
        feat[q][3] = __ldg(pp[q] + 5);
        feat[q][4] = -red[q * 6 + 0];                    // vy
        feat[q][5] = red[q * 6 + 1];                     // vx
        feat[q][6] = -red[q * 6 + 3];                    // dvy/dy
        feat[q][7] = -(red[q * 6 + 4] + red[q * 6 + 2]); // dvy/dx
        feat[q][8] = red[q * 6 + 5] + red[q * 6 + 2];    // dvx/dy
        feat[q][9] = red[q * 6 + 3];                     // dvx/dx
    }

    // ---- MLP 10 -> 100 (LeakyReLU 0.1) -> 6, weights shared across 4 i's ----
    float po[NI][6];
    #pragma unroll
    for (int q = 0; q < NI; ++q)
        #pragma unroll
        for (int m = 0; m < 6; ++m) po[q][m] = 0.0f;

    #pragma unroll
    for (int rblk = 0; rblk < 4; ++rblk) {
        int k = rblk * 32 + lane;
        if (k < HIDN) {
            float h[NI];
            float bb = __ldg(&b1[k]);
            #pragma unroll
            for (int q = 0; q < NI; ++q) h[q] = bb;
            #pragma unroll
            for (int f = 0; f < 10; ++f) {
                float w = __ldg(&W1[f * HIDN + k]);
                #pragma unroll
                for (int q = 0; q < NI; ++q) h[q] = fmaf(feat[q][f], w, h[q]);
            }
            #pragma unroll
            for (int q = 0; q < NI; ++q)
                h[q] = (h[q] >= 0.0f) ? h[q] : 0.1f * h[q];
            #pragma unroll
            for (int m = 0; m < 6; ++m) {
                float w = __ldg(&W2[k * 6 + m]);         // raw W2, L1-hot
                #pragma unroll
                for (int q = 0; q < NI; ++q) po[q][m] = fmaf(h[q], w, po[q][m]);
            }
        }
    }
    #pragma unroll
    for (int o = 16; o; o >>= 1) {
        #pragma unroll
        for (int q = 0; q < NI; ++q)
            #pragma unroll
            for (int m = 0; m < 6; ++m)
                po[q][m] += __shfl_xor_sync(0xffffffffu, po[q][m], o);
    }

    // ---- epilogue (lane 0 writes all 4 particles, float2 stores) ----
    if (lane == 0) {
        float bb0 = __ldg(&b2[0]), bb1 = __ldg(&b2[1]), bb2 = __ldg(&b2[2]);
        float bb3 = __ldg(&b2[3]), bb4 = __ldg(&b2[4]), bb5 = __ldg(&b2[5]);
        #pragma unroll
        for (int q = 0; q < NI; ++q) {
            float2* op = (float2*)(out + ((size_t)b * NPART + ibase + q) * 6);
            op[0] = make_float2(yi[q]   + 0.1f * (po[q][0] + bb0),
                                xi[q]   + 0.1f * (po[q][1] + bb1));
            op[1] = make_float2(tau_[q] + 0.1f * (po[q][2] + bb2),
                                sig_[q] + 0.1f * (po[q][3] + bb3));
            op[2] = make_float2(0.1f * softplus_fast(po[q][4] + bb4),
                                0.1f * softplus_fast(po[q][5] + bb5));
        }
    }
}

extern "C" void kernel_launch(void* const* d_in, const int* in_sizes, int n_in,
                              void* d_out, int out_size)
{
    const float* inp = (const float*)d_in[0];  // (16,512,6)
    const float* W1  = (const float*)d_in[1];  // (10,100)
    const float* b1  = (const float*)d_in[2];  // (100,)
    const float* W2  = (const float*)d_in[3];  // (100,6)
    const float* b2  = (const float*)d_in[4];  // (6,)
    float* out = (float*)d_out;                // (16,512,6)

    // single launch: 1024 blocks of 64 threads, 4 particles/warp
    dim3 grid(NB * (NPART / (WPB * NI)));      // 1024
    vortex_kernel<<<grid, TPB>>>(inp, W1, b1, W2, b2, out);
}